// round 2
// baseline (speedup 1.0000x reference)
#include <cuda_runtime.h>
#include <stdint.h>

// Problem constants (fixed shapes from reference)
#define BATCH    1024
#define NQ       300
#define NC       80
#define KTOP     300
#define NFLAT    (NQ * NC)      // 24000
#define NV4      (NFLAT / 4)    // 6000
#define NTHREADS 256
#define CAND_CAP 2048
#define SORT_N   512
#define NBINS    512
#define T_LOGIT  1.6f

__global__ __launch_bounds__(NTHREADS)
void rtdetr_post_kernel(const float* __restrict__ logits,
                        const float* __restrict__ boxes,
                        const float* __restrict__ sizes,
                        float* __restrict__ out)
{
    __shared__ unsigned long long cand[CAND_CAP];   // (logit_bits<<32)|idx
    __shared__ unsigned long long keys[SORT_N];     // (sig_bits<<32)|~idx
    __shared__ int hist[NBINS];
    __shared__ int s_nc;   // candidate count
    __shared__ int s_cut;  // cutoff bin
    __shared__ int s_n2;   // refined candidate count

    const int b   = blockIdx.x;
    const int tid = threadIdx.x;

    for (int i = tid; i < NBINS; i += NTHREADS) hist[i] = 0;
    if (tid == 0) { s_nc = 0; s_n2 = 0; }
    __syncthreads();

    const unsigned T_BITS   = __float_as_uint(T_LOGIT);
    const int      BIN_BASE = (int)(T_BITS >> 15);

    // ---- Pass 1: stream logits, keep candidates with logit > 1.6 ----
    const float4* lg4 = (const float4*)(logits + (size_t)b * NFLAT);
    for (int i = tid; i < NV4; i += NTHREADS) {
        float4 v = lg4[i];
        float vv[4] = {v.x, v.y, v.z, v.w};
        #pragma unroll
        for (int j = 0; j < 4; j++) {
            float x = vv[j];
            if (x > T_LOGIT) {
                unsigned bits = __float_as_uint(x);        // positive -> monotone bits
                int bin = (int)(bits >> 15) - BIN_BASE;
                bin = min(bin, NBINS - 1);
                atomicAdd(&hist[bin], 1);
                int p = atomicAdd(&s_nc, 1);
                if (p < CAND_CAP)
                    cand[p] = ((unsigned long long)bits << 32) | (unsigned)(i * 4 + j);
            }
        }
    }
    __syncthreads();

    // ---- Find cutoff bin (suffix scan), keep one margin bin ----
    if (tid == 0) {
        int cum = 0, cut = 0;
        for (int bb = NBINS - 1; bb >= 0; bb--) {
            cum += hist[bb];
            if (cum >= KTOP) { cut = bb; break; }
        }
        s_cut = max(cut - 1, 0);   // margin bin covers sigmoid-rounding ties
    }
    for (int i = tid; i < SORT_N; i += NTHREADS) keys[i] = 0ULL;  // padding
    __syncthreads();

    // ---- Refine: sigmoid only for survivors, pack sortable keys ----
    const int nc   = min(s_nc, CAND_CAP);
    const int cutb = s_cut;
    for (int i = tid; i < nc; i += NTHREADS) {
        unsigned long long ck = cand[i];
        unsigned bits = (unsigned)(ck >> 32);
        int bin = min((int)(bits >> 15) - BIN_BASE, NBINS - 1);
        if (bin >= cutb) {
            float x = __uint_as_float(bits);
            float s = 1.0f / (1.0f + expf(-x));
            unsigned sb  = __float_as_uint(s);
            unsigned idx = (unsigned)(ck & 0xFFFFFFFFu);
            int p = atomicAdd(&s_n2, 1);
            if (p < SORT_N)
                keys[p] = ((unsigned long long)sb << 32) | (unsigned)(~idx);
        }
    }
    __syncthreads();

    // ---- Bitonic sort 512 keys, descending (matches jax value-desc/idx-asc) ----
    for (int k = 2; k <= SORT_N; k <<= 1) {
        for (int j = k >> 1; j > 0; j >>= 1) {
            for (int i = tid; i < SORT_N; i += NTHREADS) {
                int ixj = i ^ j;
                if (ixj > i) {
                    unsigned long long a  = keys[i];
                    unsigned long long bb = keys[ixj];
                    bool desc = ((i & k) == 0);
                    if (desc ? (a < bb) : (a > bb)) {
                        keys[i]   = bb;
                        keys[ixj] = a;
                    }
                }
            }
            __syncthreads();
        }
    }

    // ---- Emit: labels | boxes | scores (flattened, in return order) ----
    const float4* bx4 = (const float4*)(boxes + (size_t)b * NQ * 4);
    const float sw = sizes[b * 2 + 0];
    const float sh = sizes[b * 2 + 1];

    float*  out_labels = out;
    float4* out_boxes  = (float4*)(out + (size_t)BATCH * KTOP);
    float*  out_scores = out + (size_t)BATCH * KTOP * 5;

    for (int i = tid; i < KTOP; i += NTHREADS) {
        unsigned long long kk = keys[i];
        unsigned sb  = (unsigned)(kk >> 32);
        unsigned idx = ~((unsigned)(kk & 0xFFFFFFFFu));
        int label = (int)(idx % NC);
        int q     = (int)(idx / NC);
        float4 cb = bx4[q];
        float x0 = (cb.x - 0.5f * cb.z) * sw;
        float y0 = (cb.y - 0.5f * cb.w) * sh;
        float x1 = (cb.x + 0.5f * cb.z) * sw;
        float y1 = (cb.y + 0.5f * cb.w) * sh;
        out_labels[b * KTOP + i] = (float)label;
        out_boxes[(size_t)b * KTOP + i] = make_float4(x0, y0, x1, y1);
        out_scores[b * KTOP + i] = __uint_as_float(sb);
    }
}

extern "C" void kernel_launch(void* const* d_in, const int* in_sizes, int n_in,
                              void* d_out, int out_size)
{
    const float* logits = (const float*)d_in[0];   // [1024,300,80] f32
    const float* boxes  = (const float*)d_in[1];   // [1024,300,4]  f32
    const float* sizes  = (const float*)d_in[2];   // [1024,2]      f32
    float* out = (float*)d_out;                    // labels|boxes|scores f32

    rtdetr_post_kernel<<<BATCH, NTHREADS>>>(logits, boxes, sizes, out);
}

// round 9
// speedup vs baseline: 1.1168x; 1.1168x over previous
#include <cuda_runtime.h>
#include <stdint.h>

#define BATCH    1024
#define NQ       300
#define NC       80
#define KTOP     300
#define NFLAT    (NQ * NC)      // 24000
#define NV4      (NFLAT / 4)    // 6000
#define NTHREADS 256
#define CAND_CAP 1792
#define SORT_N   512
#define NBINS    256
#define T_LOGIT  1.6f

__global__ __launch_bounds__(NTHREADS, 8)
void rtdetr_post_kernel(const float* __restrict__ logits,
                        const float* __restrict__ boxes,
                        const float* __restrict__ sizes,
                        float* __restrict__ out)
{
    __shared__ unsigned long long cand[CAND_CAP];   // (logit_bits<<32)|idx
    __shared__ unsigned long long keys[SORT_N];     // (sig_bits<<32)|~idx
    __shared__ int hist[NBINS];
    __shared__ int suf[NBINS];                      // suffix sums
    __shared__ int s_nc;
    __shared__ int s_cut;
    __shared__ int s_n2;

    const int b   = blockIdx.x;
    const int tid = threadIdx.x;

    hist[tid] = 0;                                  // NTHREADS == NBINS
    if (tid == 0) { s_nc = 0; s_n2 = 0; }
    __syncthreads();

    const unsigned T_BITS   = __float_as_uint(T_LOGIT);
    const int      BIN_BASE = (int)(T_BITS >> 16);

    // ---- Pass 1: stream logits; early-out on max-of-4, rare candidate push ----
    const float4* lg4 = (const float4*)(logits + (size_t)b * NFLAT);
    #pragma unroll 2
    for (int i = tid; i < NV4; i += NTHREADS) {
        float4 v = lg4[i];
        float m = fmaxf(fmaxf(v.x, v.y), fmaxf(v.z, v.w));
        if (m > T_LOGIT) {
            float vv[4] = {v.x, v.y, v.z, v.w};
            #pragma unroll
            for (int j = 0; j < 4; j++) {
                float x = vv[j];
                if (x > T_LOGIT) {
                    unsigned bits = __float_as_uint(x);   // positive -> monotone
                    int bin = min((int)(bits >> 16) - BIN_BASE, NBINS - 1);
                    atomicAdd(&hist[bin], 1);
                    int p = atomicAdd(&s_nc, 1);
                    if (p < CAND_CAP)
                        cand[p] = ((unsigned long long)bits << 32) | (unsigned)(i * 4 + j);
                }
            }
        }
    }
    __syncthreads();

    // ---- Parallel suffix scan of histogram (Hillis-Steele, 8 steps) ----
    suf[tid] = hist[tid];
    __syncthreads();
    #pragma unroll
    for (int off = 1; off < NBINS; off <<= 1) {
        int v = suf[tid] + ((tid + off < NBINS) ? suf[tid + off] : 0);
        __syncthreads();
        suf[tid] = v;
        __syncthreads();
    }
    // cutoff: largest bin t with suffix[t] >= KTOP; keep one margin bin
    {
        int st = suf[tid];
        int sn = (tid < NBINS - 1) ? suf[tid + 1] : 0;
        if (st >= KTOP && sn < KTOP) s_cut = (tid > 0) ? tid - 1 : 0;
    }
    // zero sort keys (padding)
    keys[tid]       = 0ULL;
    keys[tid + 256] = 0ULL;
    __syncthreads();

    // ---- Refine: sigmoid only for survivors ----
    const int nc   = min(s_nc, CAND_CAP);
    const int cutb = s_cut;
    for (int i = tid; i < nc; i += NTHREADS) {
        unsigned long long ck = cand[i];
        unsigned bits = (unsigned)(ck >> 32);
        int bin = min((int)(bits >> 16) - BIN_BASE, NBINS - 1);
        if (bin >= cutb) {
            float x = __uint_as_float(bits);
            float s = 1.0f / (1.0f + expf(-x));
            unsigned sb  = __float_as_uint(s);
            unsigned idx = (unsigned)(ck & 0xFFFFFFFFu);
            int p = atomicAdd(&s_n2, 1);
            if (p < SORT_N)
                keys[p] = ((unsigned long long)sb << 32) | (unsigned)(~idx);
        }
    }
    __syncthreads();

    // ---- Bitonic sort 512 desc; warp-private passes use __syncwarp ----
    for (int k = 2; k <= SORT_N; k <<= 1) {
        for (int j = k >> 1; j > 0; j >>= 1) {
            #pragma unroll
            for (int r = 0; r < 2; r++) {
                int i = tid + (r << 8);
                int ixj = i ^ j;
                if (ixj > i) {
                    unsigned long long a  = keys[i];
                    unsigned long long bb = keys[ixj];
                    bool desc = ((i & k) == 0);
                    if (desc ? (a < bb) : (a > bb)) {
                        keys[i]   = bb;
                        keys[ixj] = a;
                    }
                }
            }
            int nj = (j > 1) ? (j >> 1) : k;   // first pass of next stage has j = k
            if (j >= 32 || nj >= 32) __syncthreads();
            else                     __syncwarp();
        }
    }

    // ---- Emit: labels | boxes | scores ----
    const float4* bx4 = (const float4*)(boxes + (size_t)b * NQ * 4);
    const float sw = sizes[b * 2 + 0];
    const float sh = sizes[b * 2 + 1];

    float*  out_labels = out;
    float4* out_boxes  = (float4*)(out + (size_t)BATCH * KTOP);
    float*  out_scores = out + (size_t)BATCH * KTOP * 5;

    for (int i = tid; i < KTOP; i += NTHREADS) {
        unsigned long long kk = keys[i];
        unsigned sb  = (unsigned)(kk >> 32);
        unsigned idx = ~((unsigned)(kk & 0xFFFFFFFFu));
        int label = (int)(idx % NC);
        int q     = (int)(idx / NC);
        float4 cb = bx4[q];
        float x0 = (cb.x - 0.5f * cb.z) * sw;
        float y0 = (cb.y - 0.5f * cb.w) * sh;
        float x1 = (cb.x + 0.5f * cb.z) * sw;
        float y1 = (cb.y + 0.5f * cb.w) * sh;
        out_labels[b * KTOP + i] = (float)label;
        out_boxes[(size_t)b * KTOP + i] = make_float4(x0, y0, x1, y1);
        out_scores[b * KTOP + i] = __uint_as_float(sb);
    }
}

extern "C" void kernel_launch(void* const* d_in, const int* in_sizes, int n_in,
                              void* d_out, int out_size)
{
    const float* logits = (const float*)d_in[0];   // [1024,300,80] f32
    const float* boxes  = (const float*)d_in[1];   // [1024,300,4]  f32
    const float* sizes  = (const float*)d_in[2];   // [1024,2]      f32
    float* out = (float*)d_out;

    rtdetr_post_kernel<<<BATCH, NTHREADS>>>(logits, boxes, sizes, out);
}

// round 13
// speedup vs baseline: 1.4668x; 1.3134x over previous
#include <cuda_runtime.h>
#include <stdint.h>

#define BATCH    1024
#define NQ       300
#define NC       80
#define KTOP     300
#define NFLAT    (NQ * NC)      // 24000
#define NV4      (NFLAT / 4)    // 6000
#define NTHREADS 256
#define CAND_CAP 1792
#define SORT_N   512
#define NBINS    256
#define T_LOGIT  1.6f

// Warp-local bitonic compare-exchange via shuffle. Element index == tid for ka,
// tid+256 for kb; for j<=16 partner lane is (lane^j) in the same warp.
__device__ __forceinline__ unsigned long long cas_shfl(unsigned long long k,
                                                       int j, bool desc, int tid)
{
    unsigned long long p = __shfl_xor_sync(0xFFFFFFFFu, k, j);
    bool low      = ((tid & j) == 0);
    bool keep_max = (low == desc);
    bool pgt      = (p > k);
    return (keep_max == pgt) ? p : k;
}

__global__ __launch_bounds__(NTHREADS, 7)
void rtdetr_post_kernel(const float* __restrict__ logits,
                        const float* __restrict__ boxes,
                        const float* __restrict__ sizes,
                        float* __restrict__ out)
{
    __shared__ unsigned long long cand[CAND_CAP];   // (logit_bits<<32)|idx
    __shared__ unsigned long long keys[SORT_N];     // (sig_bits<<32)|~idx
    __shared__ int hist[NBINS];
    __shared__ int suf[NBINS];
    __shared__ int s_nc;
    __shared__ int s_cut;
    __shared__ int s_n2;

    const int b   = blockIdx.x;
    const int tid = threadIdx.x;

    hist[tid] = 0;                                  // NTHREADS == NBINS
    if (tid == 0) { s_nc = 0; s_n2 = 0; }
    __syncthreads();

    const unsigned T_BITS   = __float_as_uint(T_LOGIT);
    const int      BIN_BASE = (int)(T_BITS >> 16);

    // ---- Pass 1: stream logits; early-out on max-of-4 ----
    const float4* lg4 = (const float4*)(logits + (size_t)b * NFLAT);
    #pragma unroll 2
    for (int i = tid; i < NV4; i += NTHREADS) {
        float4 v = lg4[i];
        float m = fmaxf(fmaxf(v.x, v.y), fmaxf(v.z, v.w));
        if (m > T_LOGIT) {
            float vv[4] = {v.x, v.y, v.z, v.w};
            #pragma unroll
            for (int j = 0; j < 4; j++) {
                float x = vv[j];
                if (x > T_LOGIT) {
                    unsigned bits = __float_as_uint(x);
                    int bin = min((int)(bits >> 16) - BIN_BASE, NBINS - 1);
                    atomicAdd(&hist[bin], 1);
                    int p = atomicAdd(&s_nc, 1);
                    if (p < CAND_CAP)
                        cand[p] = ((unsigned long long)bits << 32) | (unsigned)(i * 4 + j);
                }
            }
        }
    }
    __syncthreads();

    // ---- Parallel suffix scan of histogram ----
    suf[tid] = hist[tid];
    __syncthreads();
    #pragma unroll
    for (int off = 1; off < NBINS; off <<= 1) {
        int v = suf[tid] + ((tid + off < NBINS) ? suf[tid + off] : 0);
        __syncthreads();
        suf[tid] = v;
        __syncthreads();
    }
    {
        int st = suf[tid];
        int sn = (tid < NBINS - 1) ? suf[tid + 1] : 0;
        if (st >= KTOP && sn < KTOP) s_cut = (tid > 0) ? tid - 1 : 0;
    }
    keys[tid]       = 0ULL;
    keys[tid + 256] = 0ULL;
    __syncthreads();

    // ---- Refine: sigmoid only for survivors ----
    const int nc   = min(s_nc, CAND_CAP);
    const int cutb = s_cut;
    for (int i = tid; i < nc; i += NTHREADS) {
        unsigned long long ck = cand[i];
        unsigned bits = (unsigned)(ck >> 32);
        int bin = min((int)(bits >> 16) - BIN_BASE, NBINS - 1);
        if (bin >= cutb) {
            float x = __uint_as_float(bits);
            float s = 1.0f / (1.0f + expf(-x));
            unsigned sb  = __float_as_uint(s);
            unsigned idx = (unsigned)(ck & 0xFFFFFFFFu);
            int p = atomicAdd(&s_n2, 1);
            if (p < SORT_N)
                keys[p] = ((unsigned long long)sb << 32) | (unsigned)(~idx);
        }
    }
    __syncthreads();

    // ---- Hybrid bitonic sort (512, descending) ----
    // Thread t owns elements t (ka) and t+256 (kb). j<=16 passes: register
    // shuffles (warp-local). j>=32 passes: shared memory.
    unsigned long long ka = keys[tid];
    unsigned long long kb = keys[tid + 256];

    // stages k = 2..32: fully register-resident
    #pragma unroll
    for (int k = 2; k <= 32; k <<= 1) {
        #pragma unroll
        for (int j = k >> 1; j > 0; j >>= 1) {
            bool desc = ((tid & k) == 0);   // (tid+256)&k == tid&k for k<=32
            ka = cas_shfl(ka, j, desc, tid);
            kb = cas_shfl(kb, j, desc, tid);
        }
    }

    // stages k = 64..512: j>=32 in smem, then j=16..1 in registers
    #pragma unroll
    for (int k = 64; k <= SORT_N; k <<= 1) {
        keys[tid]       = ka;
        keys[tid + 256] = kb;
        __syncthreads();
        for (int j = k >> 1; j >= 32; j >>= 1) {
            #pragma unroll
            for (int r = 0; r < 2; r++) {
                int i = tid + (r << 8);
                int ixj = i ^ j;
                if (ixj > i) {
                    unsigned long long a  = keys[i];
                    unsigned long long bb = keys[ixj];
                    bool desc = ((i & k) == 0);
                    if (desc ? (a < bb) : (a > bb)) {
                        keys[i]   = bb;
                        keys[ixj] = a;
                    }
                }
            }
            __syncthreads();
        }
        ka = keys[tid];
        kb = keys[tid + 256];
        bool desc_a = ((tid & k) == 0);
        bool desc_b = (((tid + 256) & k) == 0);
        #pragma unroll
        for (int j = 16; j > 0; j >>= 1) {
            ka = cas_shfl(ka, j, desc_a, tid);
            kb = cas_shfl(kb, j, desc_b, tid);
        }
    }

    // ---- Emit directly from registers: labels | boxes | scores ----
    const float4* bx4 = (const float4*)(boxes + (size_t)b * NQ * 4);
    const float sw = sizes[b * 2 + 0];
    const float sh = sizes[b * 2 + 1];

    float*  out_labels = out;
    float4* out_boxes  = (float4*)(out + (size_t)BATCH * KTOP);
    float*  out_scores = out + (size_t)BATCH * KTOP * 5;

    #pragma unroll
    for (int r = 0; r < 2; r++) {
        int i = tid + (r << 8);
        unsigned long long kk = (r == 0) ? ka : kb;
        if (i < KTOP) {
            unsigned sb  = (unsigned)(kk >> 32);
            unsigned idx = ~((unsigned)(kk & 0xFFFFFFFFu));
            int label = (int)(idx % NC);
            int q     = (int)(idx / NC);
            float4 cb = bx4[q];
            float x0 = (cb.x - 0.5f * cb.z) * sw;
            float y0 = (cb.y - 0.5f * cb.w) * sh;
            float x1 = (cb.x + 0.5f * cb.z) * sw;
            float y1 = (cb.y + 0.5f * cb.w) * sh;
            out_labels[b * KTOP + i] = (float)label;
            out_boxes[(size_t)b * KTOP + i] = make_float4(x0, y0, x1, y1);
            out_scores[b * KTOP + i] = __uint_as_float(sb);
        }
    }
}

extern "C" void kernel_launch(void* const* d_in, const int* in_sizes, int n_in,
                              void* d_out, int out_size)
{
    const float* logits = (const float*)d_in[0];   // [1024,300,80] f32
    const float* boxes  = (const float*)d_in[1];   // [1024,300,4]  f32
    const float* sizes  = (const float*)d_in[2];   // [1024,2]      f32
    float* out = (float*)d_out;

    rtdetr_post_kernel<<<BATCH, NTHREADS>>>(logits, boxes, sizes, out);
}